// round 3
// baseline (speedup 1.0000x reference)
#include <cuda_runtime.h>
#include <cstdint>

#define NROWS 16384
#define CDIM  256
#define KEMB  8192
#define NBATCH 16
#define HW    1024
#define OUT_N (NBATCH * CDIM * HW)   // 4194304

#define TM 128
#define TN 128
#define TK 16
#define TMP 132   // padded pitch for smem tiles

// ---------------- static device scratch (no runtime allocation) ----------------
__device__ float  g_xt[NROWS * CDIM];     // z transposed to [n][c] (BHWC)
__device__ float  g_rownorm[NROWS];       // |x|^2 per row (fp32)
__device__ int    g_idx[NROWS];           // argmin indices
__device__ double g_partial[4096];        // per-block loss partials

// ---------------- f32x2 helpers ----------------
__device__ __forceinline__ unsigned long long ffma2(unsigned long long a,
                                                    unsigned long long b,
                                                    unsigned long long c) {
    unsigned long long d;
    asm("fma.rn.f32x2 %0, %1, %2, %3;" : "=l"(d) : "l"(a), "l"(b), "l"(c));
    return d;
}
__device__ __forceinline__ unsigned long long pack2(float lo, float hi) {
    unsigned long long r;
    asm("mov.b64 %0, {%1, %2};" : "=l"(r) : "f"(lo), "f"(hi));
    return r;
}
__device__ __forceinline__ void unpack2(unsigned long long v, float& lo, float& hi) {
    asm("mov.b64 {%0, %1}, %2;" : "=f"(lo), "=f"(hi) : "l"(v));
}

// ---------------- K0: transpose z[B,C,HW] -> g_xt[n][c] ----------------
__global__ void k_transpose(const float* __restrict__ z) {
    __shared__ float t[32][33];
    int b   = blockIdx.z;
    int c0  = blockIdx.y * 32;
    int hw0 = blockIdx.x * 32;
    int tx = threadIdx.x, ty = threadIdx.y;        // (32, 8)
    #pragma unroll
    for (int i = ty; i < 32; i += 8)
        t[i][tx] = z[((size_t)(b * CDIM + c0 + i)) * HW + hw0 + tx];
    __syncthreads();
    #pragma unroll
    for (int i = ty; i < 32; i += 8)
        g_xt[((size_t)(b * HW + hw0 + i)) * CDIM + c0 + tx] = t[tx][i];
}

// ---------------- K1: |x|^2 per row (fp32 squares, double-accumulated) --------
__global__ void k_rownorm() {
    int row  = blockIdx.x * 8 + threadIdx.y;       // blockDim (32, 8)
    int lane = threadIdx.x;
    const float* r = g_xt + (size_t)row * CDIM;
    double acc = 0.0;
    #pragma unroll
    for (int h = 0; h < 2; h++) {
        float4 v = *reinterpret_cast<const float4*>(&r[h * 128 + lane * 4]);
        acc += (double)__fmul_rn(v.x, v.x);
        acc += (double)__fmul_rn(v.y, v.y);
        acc += (double)__fmul_rn(v.z, v.z);
        acc += (double)__fmul_rn(v.w, v.w);
    }
    #pragma unroll
    for (int off = 16; off > 0; off >>= 1)
        acc += __shfl_down_sync(0xffffffffu, acc, off);
    if (lane == 0) g_rownorm[row] = (float)acc;
}

// ---------------- K2: fused GEMM + exact-rounding argmin ----------------
__global__ __launch_bounds__(256) void k_gemm_argmin(const float* __restrict__ emb,
                                                     float* __restrict__ idx_out_f) {
    __shared__ union SM {
        struct { float As[2][TK][TMP]; float Bs[2][TK][TMP]; } g;
        struct { float v[TM][16]; int i[TM][16]; } red;
    } sm;

    const int tid = threadIdx.x;
    const int tx = tid & 15, ty = tid >> 4;
    const int rowBase = blockIdx.x * TM;

    float Sreg[8];
    #pragma unroll
    for (int i = 0; i < 8; i++) Sreg[i] = g_rownorm[rowBase + ty * 8 + i];

    float minv[8]; int mini[8];
    #pragma unroll
    for (int i = 0; i < 8; i++) { minv[i] = 3.4e38f; mini[i] = 0; }

    const int kq  = tid & 3;            // c sub-offset (kq*4) within chunk
    const int mA0 = tid >> 2;           // 0..63
    const int mA1 = (tid + 256) >> 2;   // 64..127

    const float* Abase = g_xt + (size_t)rowBase * CDIM;

    for (int tile = 0; tile < KEMB / TN; ++tile) {
        const float* Bbase = emb + (size_t)(tile * TN) * CDIM;

        unsigned long long acc[8][4];
        #pragma unroll
        for (int i = 0; i < 8; i++)
            #pragma unroll
            for (int p = 0; p < 4; p++) acc[i][p] = 0ull;

        // load chunk 0
        {
            float4 pa0 = *reinterpret_cast<const float4*>(&Abase[mA0 * CDIM + kq * 4]);
            float4 pa1 = *reinterpret_cast<const float4*>(&Abase[mA1 * CDIM + kq * 4]);
            float4 pb0 = *reinterpret_cast<const float4*>(&Bbase[mA0 * CDIM + kq * 4]);
            float4 pb1 = *reinterpret_cast<const float4*>(&Bbase[mA1 * CDIM + kq * 4]);
            sm.g.As[0][kq*4+0][mA0] = pa0.x; sm.g.As[0][kq*4+1][mA0] = pa0.y;
            sm.g.As[0][kq*4+2][mA0] = pa0.z; sm.g.As[0][kq*4+3][mA0] = pa0.w;
            sm.g.As[0][kq*4+0][mA1] = pa1.x; sm.g.As[0][kq*4+1][mA1] = pa1.y;
            sm.g.As[0][kq*4+2][mA1] = pa1.z; sm.g.As[0][kq*4+3][mA1] = pa1.w;
            sm.g.Bs[0][kq*4+0][mA0] = pb0.x; sm.g.Bs[0][kq*4+1][mA0] = pb0.y;
            sm.g.Bs[0][kq*4+2][mA0] = pb0.z; sm.g.Bs[0][kq*4+3][mA0] = pb0.w;
            sm.g.Bs[0][kq*4+0][mA1] = pb1.x; sm.g.Bs[0][kq*4+1][mA1] = pb1.y;
            sm.g.Bs[0][kq*4+2][mA1] = pb1.z; sm.g.Bs[0][kq*4+3][mA1] = pb1.w;
        }
        __syncthreads();

        int buf = 0;
        for (int ch = 0; ch < CDIM / TK; ++ch) {
            float4 na0, na1, nb0, nb1;
            const bool more = (ch < CDIM / TK - 1);
            if (more) {
                int c0 = (ch + 1) * TK;
                na0 = *reinterpret_cast<const float4*>(&Abase[mA0 * CDIM + c0 + kq * 4]);
                na1 = *reinterpret_cast<const float4*>(&Abase[mA1 * CDIM + c0 + kq * 4]);
                nb0 = *reinterpret_cast<const float4*>(&Bbase[mA0 * CDIM + c0 + kq * 4]);
                nb1 = *reinterpret_cast<const float4*>(&Bbase[mA1 * CDIM + c0 + kq * 4]);
            }
            #pragma unroll
            for (int k = 0; k < TK; k++) {
                float4 a0 = *reinterpret_cast<const float4*>(&sm.g.As[buf][k][ty * 8]);
                float4 a1 = *reinterpret_cast<const float4*>(&sm.g.As[buf][k][ty * 8 + 4]);
                float4 b0 = *reinterpret_cast<const float4*>(&sm.g.Bs[buf][k][tx * 8]);
                float4 b1 = *reinterpret_cast<const float4*>(&sm.g.Bs[buf][k][tx * 8 + 4]);
                unsigned long long bp0 = pack2(b0.x, b0.y);
                unsigned long long bp1 = pack2(b0.z, b0.w);
                unsigned long long bp2 = pack2(b1.x, b1.y);
                unsigned long long bp3 = pack2(b1.z, b1.w);
                float av[8] = {a0.x, a0.y, a0.z, a0.w, a1.x, a1.y, a1.z, a1.w};
                #pragma unroll
                for (int i = 0; i < 8; i++) {
                    unsigned long long ad = pack2(av[i], av[i]);
                    acc[i][0] = ffma2(ad, bp0, acc[i][0]);
                    acc[i][1] = ffma2(ad, bp1, acc[i][1]);
                    acc[i][2] = ffma2(ad, bp2, acc[i][2]);
                    acc[i][3] = ffma2(ad, bp3, acc[i][3]);
                }
            }
            if (more) {
                int nb = buf ^ 1;
                sm.g.As[nb][kq*4+0][mA0] = na0.x; sm.g.As[nb][kq*4+1][mA0] = na0.y;
                sm.g.As[nb][kq*4+2][mA0] = na0.z; sm.g.As[nb][kq*4+3][mA0] = na0.w;
                sm.g.As[nb][kq*4+0][mA1] = na1.x; sm.g.As[nb][kq*4+1][mA1] = na1.y;
                sm.g.As[nb][kq*4+2][mA1] = na1.z; sm.g.As[nb][kq*4+3][mA1] = na1.w;
                sm.g.Bs[nb][kq*4+0][mA0] = nb0.x; sm.g.Bs[nb][kq*4+1][mA0] = nb0.y;
                sm.g.Bs[nb][kq*4+2][mA0] = nb0.z; sm.g.Bs[nb][kq*4+3][mA0] = nb0.w;
                sm.g.Bs[nb][kq*4+0][mA1] = nb1.x; sm.g.Bs[nb][kq*4+1][mA1] = nb1.y;
                sm.g.Bs[nb][kq*4+2][mA1] = nb1.z; sm.g.Bs[nb][kq*4+3][mA1] = nb1.w;
                __syncthreads();
                buf ^= 1;
            }
        }

        // epilogue: distances + running argmin (first-index tie-break: strict <,
        // j scanned in ascending order)
        int jbase = tile * TN + tx * 8;
        #pragma unroll
        for (int i = 0; i < 8; i++) {
            #pragma unroll
            for (int p = 0; p < 4; p++) {
                float lo, hi;
                unpack2(acc[i][p], lo, hi);
                float dlo = __fadd_rn(Sreg[i], -__fmul_rn(2.0f, lo));
                float dhi = __fadd_rn(Sreg[i], -__fmul_rn(2.0f, hi));
                int jlo = jbase + p * 2;
                if (dlo < minv[i]) { minv[i] = dlo; mini[i] = jlo; }
                if (dhi < minv[i]) { minv[i] = dhi; mini[i] = jlo + 1; }
            }
        }
    }

    __syncthreads();  // smem about to be reused by reduction (union)
    #pragma unroll
    for (int i = 0; i < 8; i++) {
        sm.red.v[ty * 8 + i][tx] = minv[i];
        sm.red.i[ty * 8 + i][tx] = mini[i];
    }
    __syncthreads();
    if (tid < TM) {
        float bv = sm.red.v[tid][0];
        int   bi = sm.red.i[tid][0];
        #pragma unroll
        for (int t = 1; t < 16; t++) {
            float v = sm.red.v[tid][t];
            int  ii = sm.red.i[tid][t];
            if (v < bv || (v == bv && ii < bi)) { bv = v; bi = ii; }
        }
        int n = rowBase + tid;
        g_idx[n] = bi;
        idx_out_f[n] = (float)bi;
    }
}

// ---------------- K3: gather + straight-through output + loss partials --------
__global__ void k_output(const float* __restrict__ emb, float* __restrict__ out) {
    __shared__ float tile[32][33];
    __shared__ double sred[256];
    int b = blockIdx.z, c0 = blockIdx.y * 32, hw0 = blockIdx.x * 32;
    int tx = threadIdx.x, ty = threadIdx.y;        // (32, 8)
    double acc = 0.0;
    #pragma unroll
    for (int i = ty; i < 32; i += 8) {
        int n = b * HW + hw0 + i;
        int id = g_idx[n];
        float zv = g_xt[(size_t)n * CDIM + c0 + tx];
        float qv = emb[(size_t)id * CDIM + c0 + tx];
        float t  = __fsub_rn(qv, zv);      // fl(q - z), exactly as reference
        float o  = __fadd_rn(zv, t);       // fl(z + (q - z))
        tile[i][tx] = o;
        acc += (double)__fmul_rn(t, t);    // fl((q-z)^2), double-accumulated
    }
    __syncthreads();
    #pragma unroll
    for (int i = ty; i < 32; i += 8)
        out[((size_t)(b * CDIM + c0 + i)) * HW + hw0 + tx] = tile[tx][i];

    int tid = ty * 32 + tx;
    sred[tid] = acc;
    __syncthreads();
    for (int s = 128; s > 0; s >>= 1) {
        if (tid < s) sred[tid] += sred[tid + s];
        __syncthreads();
    }
    if (tid == 0)
        g_partial[blockIdx.x + 32 * (blockIdx.y + 8 * blockIdx.z)] = sred[0];
}

// ---------------- K4: final loss reduce (fixed order, deterministic) ----------
__global__ void k_loss(float* __restrict__ out_loss) {
    __shared__ double sred[256];
    int tid = threadIdx.x;
    double acc = 0.0;
    for (int q = tid; q < 4096; q += 256) acc += g_partial[q];
    sred[tid] = acc;
    __syncthreads();
    for (int s = 128; s > 0; s >>= 1) {
        if (tid < s) sred[tid] += sred[tid + s];
        __syncthreads();
    }
    if (tid == 0) {
        float m = (float)(sred[0] / (double)OUT_N);
        out_loss[0] = __fadd_rn(m, __fmul_rn(0.25f, m));   // q_loss + BETA * e_loss
    }
}

// ---------------- entry ----------------
extern "C" void kernel_launch(void* const* d_in, const int* in_sizes, int n_in,
                              void* d_out, int out_size) {
    const float* z   = (const float*)d_in[0];   // [16,256,32,32]
    const float* emb = (const float*)d_in[1];   // [8192,256]
    float* out    = (float*)d_out;              // out: [0, OUT_N)
    float* loss_p = out + OUT_N;                // loss: [OUT_N]
    float* idx_p  = out + OUT_N + 1;            // idx:  [OUT_N+1, OUT_N+1+16384)

    k_transpose<<<dim3(32, 8, 16), dim3(32, 8)>>>(z);
    k_rownorm<<<NROWS / 8, dim3(32, 8)>>>();
    k_gemm_argmin<<<NROWS / TM, 256>>>(emb, idx_p);
    k_output<<<dim3(32, 8, 16), dim3(32, 8)>>>(emb, out);
    k_loss<<<1, 256>>>(loss_p);
}

// round 5
// speedup vs baseline: 3.1631x; 3.1631x over previous
#include <cuda_runtime.h>
#include <cuda_bf16.h>
#include <cstdint>

#define NROWS 16384
#define CDIM  256
#define KEMB  8192
#define NBATCH 16
#define HW    1024
#define OUT_N (NBATCH * CDIM * HW)   // 4194304

#define NTILES 32                     // 8192 / 256 column tiles
#define MARGIN 4.0e-4f

#define PW  132                       // A/B smem pitch in 32-bit words (264 bf16)
#define DPW 261                       // D smem pitch in floats

// ---------------- static device scratch ----------------
__device__ float          g_xt[NROWS * CDIM];    // z transposed [n][c] fp32
__device__ __nv_bfloat16  g_xh[NROWS * CDIM];    // bf16(x)
__device__ __nv_bfloat16  g_eh[KEMB * CDIM];     // bf16(emb)
__device__ float          g_rownorm[NROWS];
__device__ int            g_idx[NROWS];
__device__ double         g_partial[4096];
__device__ float4         g_tv[NROWS * NTILES];  // top-4 coarse (-2*dot) per (row,tile)
__device__ int4           g_ti[NROWS * NTILES];  // matching indices

// top-4 running insert, strict < (keeps earliest-seen on ties)
#define TOP4_INSERT(dv, j)                                                    \
    if ((dv) < v3) {                                                          \
        if ((dv) < v2) {                                                      \
            v3 = v2; i3 = i2;                                                 \
            if ((dv) < v1) {                                                  \
                v2 = v1; i2 = i1;                                             \
                if ((dv) < v0) { v1 = v0; i1 = i0; v0 = (dv); i0 = (j); }     \
                else           { v1 = (dv); i1 = (j); }                       \
            } else { v2 = (dv); i2 = (j); }                                   \
        } else { v3 = (dv); i3 = (j); }                                       \
    }

// ---------------- K0: transpose z[B,C,HW] -> g_xt / g_xh ----------------
__global__ void k_transpose(const float* __restrict__ z) {
    __shared__ float t[32][33];
    int b = blockIdx.z, c0 = blockIdx.y * 32, hw0 = blockIdx.x * 32;
    int tx = threadIdx.x, ty = threadIdx.y;        // (32, 8)
    #pragma unroll
    for (int i = ty; i < 32; i += 8)
        t[i][tx] = z[((size_t)(b * CDIM + c0 + i)) * HW + hw0 + tx];
    __syncthreads();
    #pragma unroll
    for (int i = ty; i < 32; i += 8) {
        float v = t[tx][i];
        size_t o = ((size_t)(b * HW + hw0 + i)) * CDIM + c0 + tx;
        g_xt[o] = v;
        g_xh[o] = __float2bfloat16(v);
    }
}

// ---------------- K0b: emb -> bf16 ----------------
__global__ void k_ebf(const float* __restrict__ emb) {
    int i = blockIdx.x * 256 + threadIdx.x;        // over KEMB*CDIM/4
    float4 v = reinterpret_cast<const float4*>(emb)[i];
    __nv_bfloat16* o = g_eh + (size_t)i * 4;
    o[0] = __float2bfloat16(v.x); o[1] = __float2bfloat16(v.y);
    o[2] = __float2bfloat16(v.z); o[3] = __float2bfloat16(v.w);
}

// ---------------- K1: |x|^2 per row ----------------
__global__ void k_rownorm() {
    int row  = blockIdx.x * 8 + threadIdx.y;       // (32, 8)
    int lane = threadIdx.x;
    const float* r = g_xt + (size_t)row * CDIM;
    double acc = 0.0;
    #pragma unroll
    for (int h = 0; h < 2; h++) {
        float4 v = *reinterpret_cast<const float4*>(&r[h * 128 + lane * 4]);
        acc += (double)__fmul_rn(v.x, v.x);
        acc += (double)__fmul_rn(v.y, v.y);
        acc += (double)__fmul_rn(v.z, v.z);
        acc += (double)__fmul_rn(v.w, v.w);
    }
    #pragma unroll
    for (int off = 16; off > 0; off >>= 1)
        acc += __shfl_down_sync(0xffffffffu, acc, off);
    if (lane == 0) g_rownorm[row] = (float)acc;
}

// ---------------- K2: coarse bf16 mma.sync GEMM + per-tile top-4 ----------------
// CTA: 128 rows x 256 cols, K=256 resident. 512 thr = 16 warps (4m x 4n),
// warp tile 32x64 = 2 m16 x 8 n8 mma tiles, 16 k-steps of k16.
// smem (words): A [0, 16896), B [16896, 50688). Reused after mainloop:
//   D floats [0, 33408), redv [33408, 35456), redi [35456, 37504).
__global__ __launch_bounds__(512, 1) void k_gemm_coarse() {
    extern __shared__ __align__(16) uint32_t sw[];
    uint32_t* smA = sw;
    uint32_t* smB = sw + 16896;
    float*    smD = reinterpret_cast<float*>(sw);
    float*    redv = reinterpret_cast<float*>(sw) + 33408;
    int*      redi = reinterpret_cast<int*>(sw) + 35456;

    const int tid = threadIdx.x;
    const int rowBase = blockIdx.x * 128;
    const int colBase = blockIdx.y * 256;

    // ---- global -> smem (padded, coalesced 16B) ----
    const uint4* Ag = reinterpret_cast<const uint4*>(g_xh + (size_t)rowBase * CDIM);
    #pragma unroll
    for (int it = 0; it < 8; it++) {               // 128 rows * 32 chunks
        int t = tid + it * 512;
        int r = t >> 5, c = t & 31;
        *reinterpret_cast<uint4*>(&smA[r * PW + c * 4]) = Ag[t];
    }
    const uint4* Bg = reinterpret_cast<const uint4*>(g_eh + (size_t)colBase * CDIM);
    #pragma unroll
    for (int it = 0; it < 16; it++) {              // 256 rows * 32 chunks
        int t = tid + it * 512;
        int r = t >> 5, c = t & 31;
        *reinterpret_cast<uint4*>(&smB[r * PW + c * 4]) = Bg[t];
    }
    __syncthreads();

    // ---- mainloop ----
    const int lane = tid & 31, wid = tid >> 5;
    const int g = lane >> 2, m4 = lane & 3;
    const int mw = wid >> 2, nw = wid & 3;

    float c[2][8][4];
    #pragma unroll
    for (int mt = 0; mt < 2; mt++)
        #pragma unroll
        for (int nt = 0; nt < 8; nt++)
            #pragma unroll
            for (int q = 0; q < 4; q++) c[mt][nt][q] = 0.0f;

    const uint32_t* Abase = smA + (mw * 32 + g) * PW + m4;
    const uint32_t* Bbase = smB + (nw * 64 + g) * PW + m4;

    for (int ks = 0; ks < 16; ks++) {
        const int ko = ks * 8;
        uint32_t a[2][4], b[8][2];
        #pragma unroll
        for (int mt = 0; mt < 2; mt++) {
            const uint32_t* p = Abase + mt * 16 * PW + ko;
            a[mt][0] = p[0];
            a[mt][1] = p[8 * PW];
            a[mt][2] = p[4];
            a[mt][3] = p[8 * PW + 4];
        }
        #pragma unroll
        for (int nt = 0; nt < 8; nt++) {
            const uint32_t* p = Bbase + nt * 8 * PW + ko;
            b[nt][0] = p[0];
            b[nt][1] = p[4];
        }
        #pragma unroll
        for (int mt = 0; mt < 2; mt++)
            #pragma unroll
            for (int nt = 0; nt < 8; nt++)
                asm volatile(
                    "mma.sync.aligned.m16n8k16.row.col.f32.bf16.bf16.f32 "
                    "{%0,%1,%2,%3}, {%4,%5,%6,%7}, {%8,%9}, {%0,%1,%2,%3};"
                    : "+f"(c[mt][nt][0]), "+f"(c[mt][nt][1]),
                      "+f"(c[mt][nt][2]), "+f"(c[mt][nt][3])
                    : "r"(a[mt][0]), "r"(a[mt][1]), "r"(a[mt][2]), "r"(a[mt][3]),
                      "r"(b[nt][0]), "r"(b[nt][1]));
    }
    __syncthreads();   // A/B smem dead; reuse as D

    // ---- accum -> smem D ----
    #pragma unroll
    for (int mt = 0; mt < 2; mt++) {
        int row = mw * 32 + mt * 16 + g;
        #pragma unroll
        for (int nt = 0; nt < 8; nt++) {
            int col = nw * 64 + nt * 8 + m4 * 2;
            smD[row * DPW + col]           = c[mt][nt][0];
            smD[row * DPW + col + 1]       = c[mt][nt][1];
            smD[(row + 8) * DPW + col]     = c[mt][nt][2];
            smD[(row + 8) * DPW + col + 1] = c[mt][nt][3];
        }
    }
    __syncthreads();

    // ---- per-row top-4 over 64-col chunk (skewed scan: conflict-free) ----
    {
        int row = tid >> 2, ch = tid & 3;
        const float* dr = smD + row * DPW + ch * 64;
        float v0 = 1e30f, v1 = 1e30f, v2 = 1e30f, v3 = 1e30f;
        int   i0 = 0,     i1 = 0,     i2 = 0,     i3 = 0;
        #pragma unroll 8
        for (int i = 0; i < 64; i++) {
            int ii = (i + ch * 8) & 63;
            float dv = -2.0f * dr[ii];
            int j = colBase + ch * 64 + ii;
            TOP4_INSERT(dv, j);
        }
        redv[tid * 4 + 0] = v0; redv[tid * 4 + 1] = v1;
        redv[tid * 4 + 2] = v2; redv[tid * 4 + 3] = v3;
        redi[tid * 4 + 0] = i0; redi[tid * 4 + 1] = i1;
        redi[tid * 4 + 2] = i2; redi[tid * 4 + 3] = i3;
    }
    __syncthreads();

    // ---- merge 4 chunks -> per-row top-4 over 256 cols ----
    if (tid < 128) {
        float v0 = 1e30f, v1 = 1e30f, v2 = 1e30f, v3 = 1e30f;
        int   i0 = 0,     i1 = 0,     i2 = 0,     i3 = 0;
        #pragma unroll
        for (int ch = 0; ch < 4; ch++)
            #pragma unroll
            for (int q = 0; q < 4; q++) {
                int e = (tid * 4 + ch) * 4 + q;
                float dv = redv[e];
                int j = redi[e];
                TOP4_INSERT(dv, j);
            }
        int n = rowBase + tid;
        g_tv[(size_t)n * NTILES + blockIdx.y] = make_float4(v0, v1, v2, v3);
        g_ti[(size_t)n * NTILES + blockIdx.y] = make_int4(i0, i1, i2, i3);
    }
}

// ---------------- K3: exact rescore of near-min candidates ----------------
// One warp per row; 128 stored entries; rescore all within MARGIN of coarse min
// with the EXACT Round-3 fp32 chain; lexicographic (d, j) = first-index tie-break.
__global__ __launch_bounds__(128) void k_rescore(const float* __restrict__ emb,
                                                 float* __restrict__ idx_out_f) {
    int wid = threadIdx.x >> 5, lid = threadIdx.x & 31;
    int n = blockIdx.x * 4 + wid;
    const float4* tv = g_tv + (size_t)n * NTILES;
    const int4*   ti = g_ti + (size_t)n * NTILES;

    float ev[4]; int ei[4];
    #pragma unroll
    for (int q = 0; q < 4; q++) {
        int e = q * 32 + lid;                      // entry 0..127
        float4 v4 = tv[e >> 2];
        int4   i4 = ti[e >> 2];
        int rk = e & 3;
        ev[q] = (rk == 0) ? v4.x : (rk == 1) ? v4.y : (rk == 2) ? v4.z : v4.w;
        ei[q] = (rk == 0) ? i4.x : (rk == 1) ? i4.y : (rk == 2) ? i4.z : i4.w;
    }
    float m = fminf(fminf(ev[0], ev[1]), fminf(ev[2], ev[3]));
    #pragma unroll
    for (int off = 16; off > 0; off >>= 1)
        m = fminf(m, __shfl_xor_sync(0xffffffffu, m, off));

    const float S = g_rownorm[n];
    const float* xr = g_xt + (size_t)n * CDIM;
    float best = 1e30f; int bj = 0x7fffffff;
    #pragma unroll
    for (int q = 0; q < 4; q++) {
        if (ev[q] <= m + MARGIN) {
            int j = ei[q];
            const float* er = emb + (size_t)j * CDIM;
            float dot = 0.0f;
            #pragma unroll 8
            for (int k = 0; k < CDIM; k++)
                dot = __fmaf_rn(xr[k], er[k], dot);
            float d = __fadd_rn(S, -__fmul_rn(2.0f, dot));
            if (d < best || (d == best && j < bj)) { best = d; bj = j; }
        }
    }
    #pragma unroll
    for (int off = 16; off > 0; off >>= 1) {
        float ov = __shfl_xor_sync(0xffffffffu, best, off);
        int   oj = __shfl_xor_sync(0xffffffffu, bj,   off);
        if (ov < best || (ov == best && oj < bj)) { best = ov; bj = oj; }
    }
    if (lid == 0) {
        g_idx[n] = bj;
        idx_out_f[n] = (float)bj;
    }
}

// ---------------- K4: gather + straight-through output + loss partials --------
__global__ void k_output(const float* __restrict__ emb, float* __restrict__ out) {
    __shared__ float tile[32][33];
    __shared__ double sred[256];
    int b = blockIdx.z, c0 = blockIdx.y * 32, hw0 = blockIdx.x * 32;
    int tx = threadIdx.x, ty = threadIdx.y;        // (32, 8)
    double acc = 0.0;
    #pragma unroll
    for (int i = ty; i < 32; i += 8) {
        int n = b * HW + hw0 + i;
        int id = g_idx[n];
        float zv = g_xt[(size_t)n * CDIM + c0 + tx];
        float qv = emb[(size_t)id * CDIM + c0 + tx];
        float t  = __fsub_rn(qv, zv);
        float o  = __fadd_rn(zv, t);
        tile[i][tx] = o;
        acc += (double)__fmul_rn(t, t);
    }
    __syncthreads();
    #pragma unroll
    for (int i = ty; i < 32; i += 8)
        out[((size_t)(b * CDIM + c0 + i)) * HW + hw0 + tx] = tile[tx][i];

    int tid = ty * 32 + tx;
    sred[tid] = acc;
    __syncthreads();
    for (int s = 128; s > 0; s >>= 1) {
        if (tid < s) sred[tid] += sred[tid + s];
        __syncthreads();
    }
    if (tid == 0)
        g_partial[blockIdx.x + 32 * (blockIdx.y + 8 * blockIdx.z)] = sred[0];
}

// ---------------- K5: final loss reduce ----------------
__global__ void k_loss(float* __restrict__ out_loss) {
    __shared__ double sred[256];
    int tid = threadIdx.x;
    double acc = 0.0;
    for (int q = tid; q < 4096; q += 256) acc += g_partial[q];
    sred[tid] = acc;
    __syncthreads();
    for (int s = 128; s > 0; s >>= 1) {
        if (tid < s) sred[tid] += sred[tid + s];
        __syncthreads();
    }
    if (tid == 0) {
        float m = (float)(sred[0] / (double)OUT_N);
        out_loss[0] = __fadd_rn(m, __fmul_rn(0.25f, m));
    }
}

// ---------------- entry ----------------
#define GEMM_SMEM (50688 * 4)   // 202752 bytes

extern "C" void kernel_launch(void* const* d_in, const int* in_sizes, int n_in,
                              void* d_out, int out_size) {
    const float* z   = (const float*)d_in[0];
    const float* emb = (const float*)d_in[1];
    float* out    = (float*)d_out;
    float* loss_p = out + OUT_N;
    float* idx_p  = out + OUT_N + 1;

    cudaFuncSetAttribute(k_gemm_coarse,
                         cudaFuncAttributeMaxDynamicSharedMemorySize, GEMM_SMEM);

    k_transpose<<<dim3(32, 8, 16), dim3(32, 8)>>>(z);
    k_ebf<<<(KEMB * CDIM / 4) / 256, 256>>>(emb);
    k_rownorm<<<NROWS / 8, dim3(32, 8)>>>();
    k_gemm_coarse<<<dim3(NROWS / 128, KEMB / 256), 512, GEMM_SMEM>>>();
    k_rescore<<<NROWS / 4, 128>>>(emb, idx_p);
    k_output<<<dim3(32, 8, 16), dim3(32, 8)>>>(emb, out);
    k_loss<<<1, 256>>>(loss_p);
}